// round 1
// baseline (speedup 1.0000x reference)
#include <cuda_runtime.h>
#include <cstdint>

// Problem constants (from reference)
#define Bk 4
#define Ck 256
#define Hk 96
#define Wk 160
#define HWk (Hk * Wk)            // 15360
#define Dk 4
#define PPk 81

// Tiling
#define TW 32                    // tile width (pixels)
#define TH 8                     // tile height (pixels)
#define KC 8                     // channels per chunk
#define NCH (Ck / KC)            // 32 chunks
#define NTHREADS 288             // 9 warps: warp w handles dy = w-4

// Padded shared rows (bank-conflict-free for the 2-row LDS.128 phases)
#define S0R 36                   // f0 tile row: 32 cols + pad
#define S1R 44                   // f1 tile row: 40 cols + pad
#define S0SZ (KC * TH * S0R)     // 2304 floats
#define S1SZ (KC * 16 * S1R)     // 5632 floats
#define BUFSZ (S0SZ + S1SZ)      // 7936 floats
#define SMEM_FLOATS (2 * BUFSZ)  // double buffered: 15872 floats = 63488 B

__device__ __forceinline__ void cp_async16(unsigned saddr, const void* g) {
    asm volatile("cp.async.cg.shared.global [%0], [%1], 16;\n" ::"r"(saddr), "l"(g));
}
__device__ __forceinline__ void cp_async8(unsigned saddr, const void* g, int sz) {
    // sz = 8 (copy) or 0 (zero-fill, no gmem read)
    asm volatile("cp.async.ca.shared.global [%0], [%1], 8, %2;\n" ::"r"(saddr), "l"(g), "r"(sz));
}

__global__ void __launch_bounds__(NTHREADS)
corr_kernel(const float* __restrict__ f0, const float* __restrict__ f1,
            float* __restrict__ out) {
    extern __shared__ float smem[];

    const int t    = threadIdx.x;
    const int x0   = blockIdx.x * TW;
    const int y0   = blockIdx.y * TH;
    const int b    = blockIdx.z;

    const int warp = t >> 5;      // 0..8  -> dy = warp - 4
    const int lane = t & 31;
    const int r    = lane >> 2;   // 0..7  tile row
    const int xs   = lane & 3;    // 0..3  x-segment (8 px each)

    const float* f0b = f0 + (size_t)b * Ck * HWk;
    const float* f1b = f1 + (size_t)b * Ck * HWk;

    float acc[8][9];
#pragma unroll
    for (int i = 0; i < 8; i++)
#pragma unroll
        for (int j = 0; j < 9; j++) acc[i][j] = 0.0f;

    // ---- cooperative chunk prefetch (cp.async, zero-fill halo) ----
    auto prefetch = [&](int c0, int bsel) {
        float* s0 = smem + bsel * BUFSZ;
        float* s1 = s0 + S0SZ;
        // f0 tile: KC x TH x 32  -> 512 float4 transfers
#pragma unroll
        for (int i = 0; i < 2; i++) {
            int idx = t + i * NTHREADS;
            if (idx < 512) {
                int c   = idx >> 6;           // /64
                int rem = idx & 63;
                int row = rem >> 3;
                int col = (rem & 7) << 2;
                const float* g = f0b + ((size_t)(c0 + c) * Hk + (y0 + row)) * Wk + x0 + col;
                unsigned sa = (unsigned)__cvta_generic_to_shared(s0 + (c * TH + row) * S0R + col);
                cp_async16(sa, g);
            }
        }
        // f1 tile: KC x 16 x 40 -> 2560 float2 transfers (x0-4 is even -> 8B aligned)
#pragma unroll
        for (int i = 0; i < 9; i++) {
            int idx = t + i * NTHREADS;
            if (idx < 2560) {
                int c    = idx / 320;
                int rem  = idx - c * 320;
                int row  = rem / 20;          // 0..15
                int col2 = rem - row * 20;    // 0..19
                int col  = col2 * 2;          // 0..38
                int gy   = y0 - 4 + row;
                int gx   = x0 - 4 + col;      // even; pair (gx,gx+1) uniformly in/out of bounds
                bool ok  = (gy >= 0) && (gy < Hk) && (gx >= 0) && (gx < Wk);
                int gyc  = gy < 0 ? 0 : (gy >= Hk ? Hk - 1 : gy);
                int gxc  = gx < 0 ? 0 : (gx >= Wk ? Wk - 2 : gx);
                const float* g = f1b + ((size_t)(c0 + c) * Hk + gyc) * Wk + gxc;
                unsigned sa = (unsigned)__cvta_generic_to_shared(s1 + (c * 16 + row) * S1R + col);
                cp_async8(sa, g, ok ? 8 : 0);
            }
        }
        asm volatile("cp.async.commit_group;\n" ::: "memory");
    };

    prefetch(0, 0);

#pragma unroll 1
    for (int k = 0; k < NCH; k++) {
        if (k + 1 < NCH) {
            prefetch((k + 1) * KC, (k + 1) & 1);
            asm volatile("cp.async.wait_group 1;\n" ::: "memory");
        } else {
            asm volatile("cp.async.wait_group 0;\n" ::: "memory");
        }
        __syncthreads();

        const float* s0 = smem + (k & 1) * BUFSZ;
        const float* s1 = s0 + S0SZ;

#pragma unroll
        for (int c = 0; c < KC; c++) {
            // 16-float f1 window for this (dy, row, xseg): rows r+warp in [0,16)
            float w[16];
            const float* wp = s1 + (c * 16 + r + warp) * S1R + xs * 8;
            *(float4*)&w[0]  = *(const float4*)&wp[0];
            *(float4*)&w[4]  = *(const float4*)&wp[4];
            *(float4*)&w[8]  = *(const float4*)&wp[8];
            *(float4*)&w[12] = *(const float4*)&wp[12];
            // 8 f0 pixels
            float a[8];
            const float* fp = s0 + (c * TH + r) * S0R + xs * 8;
            *(float4*)&a[0] = *(const float4*)&fp[0];
            *(float4*)&a[4] = *(const float4*)&fp[4];
#pragma unroll
            for (int px = 0; px < 8; px++)
#pragma unroll
                for (int j = 0; j < 9; j++)
                    acc[px][j] = fmaf(a[px], w[px + j], acc[px][j]);
        }
        __syncthreads();
    }

    // ---- epilogue: out[b, warp*9+j, y0+r, x0+xs*8+px] ----
    float* ob = out + (((size_t)b * PPk + warp * 9) * Hk + (y0 + r)) * Wk + x0 + xs * 8;
#pragma unroll
    for (int j = 0; j < 9; j++) {
        float* p = ob + (size_t)j * HWk;
        *(float4*)p       = make_float4(acc[0][j], acc[1][j], acc[2][j], acc[3][j]);
        *((float4*)p + 1) = make_float4(acc[4][j], acc[5][j], acc[6][j], acc[7][j]);
    }
}

extern "C" void kernel_launch(void* const* d_in, const int* in_sizes, int n_in,
                              void* d_out, int out_size) {
    const float* f0 = (const float*)d_in[0];
    const float* f1 = (const float*)d_in[1];
    float* out      = (float*)d_out;

    const int smem_bytes = SMEM_FLOATS * sizeof(float);  // 63488
    cudaFuncSetAttribute(corr_kernel, cudaFuncAttributeMaxDynamicSharedMemorySize, smem_bytes);

    dim3 grid(Wk / TW, Hk / TH, Bk);  // (5, 12, 4) = 240 blocks
    corr_kernel<<<grid, NTHREADS, smem_bytes>>>(f0, f1, out);
}